// round 1
// baseline (speedup 1.0000x reference)
#include <cuda_runtime.h>
#include <cuda_fp16.h>
#include <cstdint>

#define BATCH 16
#define SEQ   2048
#define DIM   128
#define TQ    128      // q rows per CTA
#define TK    64       // k rows per tile
#define THREADS 256
#define SCALE 0.08838834764831845f   // 1/sqrt(128)

// smem row strides (in elements) — padded to dodge bank conflicts
#define QS  136   // halfs per Q row   (128 + 8)
#define KS  136   // halfs per K row
#define VS  72    // halfs per Vt row  (64 + 8)
#define PSS 68    // floats per P row  (64 + 4)

// smem byte offsets (all 16B aligned)
#define OFF_Q 0
#define OFF_K (OFF_Q + TQ*QS*2)        // 34816
#define OFF_V (OFF_K + TK*KS*2)        // 52224
#define OFF_P (OFF_V + DIM*VS*2)       // 70656
#define OFF_R (OFF_P + TQ*PSS*4)       // 105472
#define SMEM_BYTES (OFF_R + TQ*4)      // 105984

__device__ __forceinline__ void mma16816(float* c,
    uint32_t a0, uint32_t a1, uint32_t a2, uint32_t a3,
    uint32_t b0, uint32_t b1)
{
    asm volatile(
        "mma.sync.aligned.m16n8k16.row.col.f32.f16.f16.f32 "
        "{%0,%1,%2,%3}, {%4,%5,%6,%7}, {%8,%9}, {%0,%1,%2,%3};\n"
        : "+f"(c[0]), "+f"(c[1]), "+f"(c[2]), "+f"(c[3])
        : "r"(a0), "r"(a1), "r"(a2), "r"(a3), "r"(b0), "r"(b1));
}

__device__ __forceinline__ uint32_t pack_f2(float x, float y) {
    __half2 h = __floats2half2_rn(x, y);
    return *reinterpret_cast<uint32_t*>(&h);
}

__global__ __launch_bounds__(THREADS, 1)
void attn_kernel(const float* __restrict__ q, const float* __restrict__ k,
                 const float* __restrict__ v, float* __restrict__ ctx,
                 float* __restrict__ attn)
{
    extern __shared__ char smem[];
    __half* Qh = reinterpret_cast<__half*>(smem + OFF_Q);
    __half* Kt = reinterpret_cast<__half*>(smem + OFF_K);
    __half* Vt = reinterpret_cast<__half*>(smem + OFF_V);
    float*  Ps = reinterpret_cast<float*>(smem + OFF_P);
    float*  RI = reinterpret_cast<float*>(smem + OFF_R);

    const int b    = blockIdx.y;
    const int q0   = blockIdx.x * TQ;
    const int tid  = threadIdx.x;
    const int w    = tid >> 5;
    const int lane = tid & 31;
    const int g    = lane >> 2;   // groupID (row within mma tile)
    const int t    = lane & 3;    // threadID in group

    // ---- load Q tile [TQ, DIM] fp32 -> fp16 smem ----
    const float* qbase = q + ((size_t)(b * SEQ + q0)) * DIM;
    for (int i = tid; i < TQ * (DIM / 4); i += THREADS) {
        int r = i >> 5, c4 = (i & 31) << 2;
        float4 f = *(const float4*)(qbase + r * DIM + c4);
        __half* dst = Qh + r * QS + c4;
        dst[0] = __float2half_rn(f.x); dst[1] = __float2half_rn(f.y);
        dst[2] = __float2half_rn(f.z); dst[3] = __float2half_rn(f.w);
    }

    const float* kbatch = k + ((size_t)b * SEQ) * DIM;
    const float* vbatch = v + ((size_t)b * SEQ) * DIM;

    // ================= SWEEP 1: row sums of exp(scores) =================
    // warp w owns score rows [w*16, w*16+16)
    const int m0 = w * 16;
    float rs0 = 0.f, rs1 = 0.f;   // rows m0+g and m0+g+8

    for (int kt = 0; kt < SEQ / TK; ++kt) {
        __syncthreads();
        const float* kb = kbatch + (size_t)kt * TK * DIM;
        for (int i = tid; i < TK * (DIM / 4); i += THREADS) {
            int r = i >> 5, c4 = (i & 31) << 2;
            float4 f = *(const float4*)(kb + r * DIM + c4);
            __half* dst = Kt + r * KS + c4;
            dst[0] = __float2half_rn(f.x); dst[1] = __float2half_rn(f.y);
            dst[2] = __float2half_rn(f.z); dst[3] = __float2half_rn(f.w);
        }
        __syncthreads();

        float acc[8][4];
        #pragma unroll
        for (int nb = 0; nb < 8; ++nb) { acc[nb][0]=acc[nb][1]=acc[nb][2]=acc[nb][3]=0.f; }

        #pragma unroll
        for (int kb2 = 0; kb2 < 8; ++kb2) {
            const int c0 = kb2 * 16 + t * 2;
            uint32_t a0 = *(const uint32_t*)(Qh + (m0 + g    ) * QS + c0);
            uint32_t a1 = *(const uint32_t*)(Qh + (m0 + g + 8) * QS + c0);
            uint32_t a2 = *(const uint32_t*)(Qh + (m0 + g    ) * QS + c0 + 8);
            uint32_t a3 = *(const uint32_t*)(Qh + (m0 + g + 8) * QS + c0 + 8);
            #pragma unroll
            for (int nb = 0; nb < 8; ++nb) {
                uint32_t b0 = *(const uint32_t*)(Kt + (nb * 8 + g) * KS + c0);
                uint32_t b1 = *(const uint32_t*)(Kt + (nb * 8 + g) * KS + c0 + 8);
                mma16816(acc[nb], a0, a1, a2, a3, b0, b1);
            }
        }
        #pragma unroll
        for (int nb = 0; nb < 8; ++nb) {
            rs0 += __expf(acc[nb][0] * SCALE) + __expf(acc[nb][1] * SCALE);
            rs1 += __expf(acc[nb][2] * SCALE) + __expf(acc[nb][3] * SCALE);
        }
    }
    rs0 += __shfl_xor_sync(0xffffffffu, rs0, 1);
    rs0 += __shfl_xor_sync(0xffffffffu, rs0, 2);
    rs1 += __shfl_xor_sync(0xffffffffu, rs1, 1);
    rs1 += __shfl_xor_sync(0xffffffffu, rs1, 2);
    if (t == 0) { RI[m0 + g] = rs0; RI[m0 + g + 8] = rs1; }
    __syncthreads();
    if (tid < TQ) RI[tid] = 1.f / RI[tid];
    __syncthreads();

    const float inv0 = RI[m0 + g];
    const float inv1 = RI[m0 + g + 8];

    // ================= SWEEP 2: recompute, write attention, P@V =================
    // context partition: warp covers rows [(w&3)*32, +32), cols [(w>>2)*64, +64)
    const int mw  = (w & 3) * 32;
    const int nwc = (w >> 2) * 64;
    float cacc[2][8][4];
    #pragma unroll
    for (int mb = 0; mb < 2; ++mb)
        #pragma unroll
        for (int nb = 0; nb < 8; ++nb) { cacc[mb][nb][0]=cacc[mb][nb][1]=cacc[mb][nb][2]=cacc[mb][nb][3]=0.f; }

    float* attnbase = attn + ((size_t)(b * SEQ + q0)) * SEQ;

    for (int kt = 0; kt < SEQ / TK; ++kt) {
        __syncthreads();   // protect Kt/Vt rewrite until all warps finished prior PV
        const float* kb = kbatch + (size_t)kt * TK * DIM;
        for (int i = tid; i < TK * (DIM / 4); i += THREADS) {
            int r = i >> 5, c4 = (i & 31) << 2;
            float4 f = *(const float4*)(kb + r * DIM + c4);
            __half* dst = Kt + r * KS + c4;
            dst[0] = __float2half_rn(f.x); dst[1] = __float2half_rn(f.y);
            dst[2] = __float2half_rn(f.z); dst[3] = __float2half_rn(f.w);
        }
        const float* vb = vbatch + (size_t)kt * TK * DIM;
        for (int i = tid; i < TK * DIM; i += THREADS) {
            int s = i >> 7, d = i & 127;
            Vt[d * VS + s] = __float2half_rn(vb[i]);   // transpose: Vt[d][s]
        }
        __syncthreads();

        // recompute scores for rows m0..m0+15 (identical to sweep1 -> deterministic)
        float acc[8][4];
        #pragma unroll
        for (int nb = 0; nb < 8; ++nb) { acc[nb][0]=acc[nb][1]=acc[nb][2]=acc[nb][3]=0.f; }
        #pragma unroll
        for (int kb2 = 0; kb2 < 8; ++kb2) {
            const int c0 = kb2 * 16 + t * 2;
            uint32_t a0 = *(const uint32_t*)(Qh + (m0 + g    ) * QS + c0);
            uint32_t a1 = *(const uint32_t*)(Qh + (m0 + g + 8) * QS + c0);
            uint32_t a2 = *(const uint32_t*)(Qh + (m0 + g    ) * QS + c0 + 8);
            uint32_t a3 = *(const uint32_t*)(Qh + (m0 + g + 8) * QS + c0 + 8);
            #pragma unroll
            for (int nb = 0; nb < 8; ++nb) {
                uint32_t b0 = *(const uint32_t*)(Kt + (nb * 8 + g) * KS + c0);
                uint32_t b1 = *(const uint32_t*)(Kt + (nb * 8 + g) * KS + c0 + 8);
                mma16816(acc[nb], a0, a1, a2, a3, b0, b1);
            }
        }
        // normalized probabilities -> Ps (fp32)
        #pragma unroll
        for (int nb = 0; nb < 8; ++nb) {
            float2 p01, p23;
            p01.x = __expf(acc[nb][0] * SCALE) * inv0;
            p01.y = __expf(acc[nb][1] * SCALE) * inv0;
            p23.x = __expf(acc[nb][2] * SCALE) * inv1;
            p23.y = __expf(acc[nb][3] * SCALE) * inv1;
            *(float2*)(Ps + (m0 + g    ) * PSS + nb * 8 + t * 2) = p01;
            *(float2*)(Ps + (m0 + g + 8) * PSS + nb * 8 + t * 2) = p23;
        }
        __syncthreads();

        // coalesced attention write (streaming, bypass L2 persistence)
        float* ab = attnbase + kt * TK;
        for (int i = tid; i < TQ * TK; i += THREADS) {
            int r = i >> 6, c = i & 63;
            __stcs(ab + (size_t)r * SEQ + c, Ps[r * PSS + c]);
        }

        // P @ V accumulate into cacc
        #pragma unroll
        for (int kb2 = 0; kb2 < 4; ++kb2) {
            const int c0 = kb2 * 16 + t * 2;
            uint32_t A[2][4];
            #pragma unroll
            for (int mb = 0; mb < 2; ++mb) {
                const int rr = mw + mb * 16 + g;
                float2 f;
                f = *(const float2*)(Ps + rr       * PSS + c0);     A[mb][0] = pack_f2(f.x, f.y);
                f = *(const float2*)(Ps + (rr + 8) * PSS + c0);     A[mb][1] = pack_f2(f.x, f.y);
                f = *(const float2*)(Ps + rr       * PSS + c0 + 8); A[mb][2] = pack_f2(f.x, f.y);
                f = *(const float2*)(Ps + (rr + 8) * PSS + c0 + 8); A[mb][3] = pack_f2(f.x, f.y);
            }
            #pragma unroll
            for (int nb = 0; nb < 8; ++nb) {
                const __half* vp = Vt + (nwc + nb * 8 + g) * VS + c0;
                uint32_t b0 = *(const uint32_t*)(vp);
                uint32_t b1 = *(const uint32_t*)(vp + 8);
                mma16816(cacc[0][nb], A[0][0], A[0][1], A[0][2], A[0][3], b0, b1);
                mma16816(cacc[1][nb], A[1][0], A[1][1], A[1][2], A[1][3], b0, b1);
            }
        }
    }

    // ---- write context ----
    float* cbase = ctx + ((size_t)(b * SEQ + q0)) * DIM;
    #pragma unroll
    for (int mb = 0; mb < 2; ++mb) {
        #pragma unroll
        for (int nb = 0; nb < 8; ++nb) {
            const int rr = mw + mb * 16 + g;
            const int cc = nwc + nb * 8 + t * 2;
            float2 lo; lo.x = cacc[mb][nb][0]; lo.y = cacc[mb][nb][1];
            float2 hi; hi.x = cacc[mb][nb][2]; hi.y = cacc[mb][nb][3];
            *(float2*)(cbase + (size_t)rr       * DIM + cc) = lo;
            *(float2*)(cbase + (size_t)(rr + 8) * DIM + cc) = hi;
        }
    }
}

extern "C" void kernel_launch(void* const* d_in, const int* in_sizes, int n_in,
                              void* d_out, int out_size)
{
    const float* q = (const float*)d_in[0];
    const float* k = (const float*)d_in[1];
    const float* v = (const float*)d_in[2];
    float* out  = (float*)d_out;
    float* ctx  = out;                                    // [16,2048,128]
    float* attn = out + (size_t)BATCH * SEQ * DIM;        // [16,2048,2048]

    cudaFuncSetAttribute(attn_kernel, cudaFuncAttributeMaxDynamicSharedMemorySize, SMEM_BYTES);
    dim3 grid(SEQ / TQ, BATCH);
    attn_kernel<<<grid, THREADS, SMEM_BYTES>>>(q, k, v, ctx, attn);
}

// round 3
// speedup vs baseline: 1.8715x; 1.8715x over previous
#include <cuda_runtime.h>
#include <cuda_fp16.h>
#include <cstdint>

#define BATCH 16
#define SEQ   2048
#define DIM   128
#define TQ    128
#define TK    64
#define THREADS 512
#define NTILE (SEQ/TK)
#define SCALE 0.08838834764831845f   // 1/sqrt(128)

// smem strides (elements)
#define QS  136   // halfs per Q row
#define KS  136   // halfs per K row
#define VHS 136   // halfs per V row = 272B = 17*16B: ldmatrix rows 16B-aligned, conflict-free
#define PSS 68    // floats per P row

// smem layout (bytes)
#define OFF_Q  0
#define SZ_Q   (TQ*QS*2)                  // 34816
#define OFF_K  (OFF_Q + SZ_Q)             // K double buffer
#define SZ_KB  (TK*KS*2)                  // 17408
#define OFF_V  (OFF_K + 2*SZ_KB)          // V double buffer (untransposed [s][d])
#define SZ_VB  (TK*VHS*2)                 // 17408
#define OFF_P  (OFF_V + 2*SZ_VB)
#define SZ_P   (TQ*PSS*4)                 // 34816
#define OFF_R  (OFF_P + SZ_P)
#define OFF_SK (OFF_R + 512)              // fp32 staging for cp.async (16B aligned)
#define OFF_SV (OFF_SK + TK*DIM*4)
#define SMEM_BYTES (OFF_SV + TK*DIM*4)    // 205312

__device__ __forceinline__ void mma16816(float* c,
    uint32_t a0, uint32_t a1, uint32_t a2, uint32_t a3,
    uint32_t b0, uint32_t b1)
{
    asm volatile(
        "mma.sync.aligned.m16n8k16.row.col.f32.f16.f16.f32 "
        "{%0,%1,%2,%3}, {%4,%5,%6,%7}, {%8,%9}, {%0,%1,%2,%3};\n"
        : "+f"(c[0]), "+f"(c[1]), "+f"(c[2]), "+f"(c[3])
        : "r"(a0), "r"(a1), "r"(a2), "r"(a3), "r"(b0), "r"(b1));
}

__device__ __forceinline__ void ldmx2t(uint32_t& b0, uint32_t& b1, const __half* p) {
    uint32_t s = (uint32_t)__cvta_generic_to_shared(p);
    asm volatile("ldmatrix.sync.aligned.m8n8.x2.trans.shared.b16 {%0,%1}, [%2];"
        : "=r"(b0), "=r"(b1) : "r"(s));
}

__device__ __forceinline__ void cp16(void* smem_dst, const void* gptr) {
    uint32_t s = (uint32_t)__cvta_generic_to_shared(smem_dst);
    asm volatile("cp.async.cg.shared.global [%0], [%1], 16;" :: "r"(s), "l"(gptr));
}
#define CP_COMMIT() asm volatile("cp.async.commit_group;")
#define CP_WAIT0()  asm volatile("cp.async.wait_group 0;" ::: "memory")

__device__ __forceinline__ uint32_t pack_f2(float x, float y) {
    __half2 h = __floats2half2_rn(x, y);
    return *reinterpret_cast<uint32_t*>(&h);
}

// issue 2048 x 16B chunks: tile is TK*DIM fp32, linear
__device__ __forceinline__ void issue_tile(char* stage, const float* g, int tid) {
    #pragma unroll
    for (int j = 0; j < 4; ++j) {
        int i = tid + j * THREADS;
        cp16(stage + i * 16, g + i * 4);
    }
}

// convert own chunks fp32 stage -> fp16 tile buffer (row stride rs halfs)
__device__ __forceinline__ void conv_tile(const float* stage, __half* dst, int rs, int tid) {
    #pragma unroll
    for (int j = 0; j < 4; ++j) {
        int i = tid + j * THREADS;
        float4 f = ((const float4*)stage)[i];
        int r = i >> 5, c4 = (i & 31) << 2;
        __half2 h0 = __floats2half2_rn(f.x, f.y);
        __half2 h1 = __floats2half2_rn(f.z, f.w);
        uint2 u; u.x = *(uint32_t*)&h0; u.y = *(uint32_t*)&h1;
        *(uint2*)(dst + r * rs + c4) = u;
    }
}

__global__ __launch_bounds__(THREADS, 1)
void attn_kernel(const float* __restrict__ q, const float* __restrict__ k,
                 const float* __restrict__ v, float* __restrict__ ctx,
                 float* __restrict__ attn)
{
    extern __shared__ char smem[];
    __half* Qh  = reinterpret_cast<__half*>(smem + OFF_Q);
    __half* Kt0 = reinterpret_cast<__half*>(smem + OFF_K);
    __half* Vh0 = reinterpret_cast<__half*>(smem + OFF_V);
    float*  Ps  = reinterpret_cast<float*>(smem + OFF_P);
    float*  RI  = reinterpret_cast<float*>(smem + OFF_R);
    float*  stK = reinterpret_cast<float*>(smem + OFF_SK);
    float*  stV = reinterpret_cast<float*>(smem + OFF_SV);

    const int b    = blockIdx.y;
    const int q0   = blockIdx.x * TQ;
    const int tid  = threadIdx.x;
    const int w    = tid >> 5;
    const int lane = tid & 31;
    const int g    = lane >> 2;
    const int t    = lane & 3;
    const int lr   = lane & 15;           // ldmatrix row lane

    // QK split: warp pair per 16-row block; each warp half the columns
    const int m0 = (w >> 1) * 16;
    const int nh = (w & 1);               // column half (nb = nh*4 + j)

    if (tid < TQ) RI[tid] = 0.f;

    // ---- Q tile load+convert (direct) ----
    const float* qbase = q + ((size_t)(b * SEQ + q0)) * DIM;
    for (int i = tid; i < TQ * (DIM / 4); i += THREADS) {
        int r = i >> 5, c4 = (i & 31) << 2;
        float4 f = *(const float4*)(qbase + r * DIM + c4);
        __half2 h0 = __floats2half2_rn(f.x, f.y);
        __half2 h1 = __floats2half2_rn(f.z, f.w);
        uint2 u; u.x = *(uint32_t*)&h0; u.y = *(uint32_t*)&h1;
        *(uint2*)(Qh + r * QS + c4) = u;
    }

    const float* kbatch = k + ((size_t)b * SEQ) * DIM;
    const float* vbatch = v + ((size_t)b * SEQ) * DIM;

    // ================= SWEEP 1: row sums =================
    issue_tile((char*)stK, kbatch, tid); CP_COMMIT();
    CP_WAIT0();
    conv_tile(stK, Kt0, KS, tid);
    __syncthreads();
    issue_tile((char*)stK, kbatch + (size_t)TK * DIM, tid); CP_COMMIT();

    float rs0 = 0.f, rs1 = 0.f;

    for (int kt = 0; kt < NTILE; ++kt) {
        __half* Kc = Kt0 + (kt & 1) * (SZ_KB / 2);
        float acc[4][4];
        #pragma unroll
        for (int j = 0; j < 4; ++j) { acc[j][0]=acc[j][1]=acc[j][2]=acc[j][3]=0.f; }

        #pragma unroll
        for (int kb2 = 0; kb2 < 8; ++kb2) {
            const int c0 = kb2 * 16 + t * 2;
            uint32_t a0 = *(const uint32_t*)(Qh + (m0 + g    ) * QS + c0);
            uint32_t a1 = *(const uint32_t*)(Qh + (m0 + g + 8) * QS + c0);
            uint32_t a2 = *(const uint32_t*)(Qh + (m0 + g    ) * QS + c0 + 8);
            uint32_t a3 = *(const uint32_t*)(Qh + (m0 + g + 8) * QS + c0 + 8);
            #pragma unroll
            for (int j = 0; j < 4; ++j) {
                const int n = (nh * 4 + j) * 8 + g;
                uint32_t b0 = *(const uint32_t*)(Kc + n * KS + c0);
                uint32_t b1 = *(const uint32_t*)(Kc + n * KS + c0 + 8);
                mma16816(acc[j], a0, a1, a2, a3, b0, b1);
            }
        }
        #pragma unroll
        for (int j = 0; j < 4; ++j) {
            rs0 += __expf(acc[j][0] * SCALE) + __expf(acc[j][1] * SCALE);
            rs1 += __expf(acc[j][2] * SCALE) + __expf(acc[j][3] * SCALE);
        }

        if (kt < NTILE - 1) {
            CP_WAIT0();
            conv_tile(stK, Kt0 + ((kt + 1) & 1) * (SZ_KB / 2), KS, tid);
        }
        __syncthreads();
        if (kt < NTILE - 2) {
            issue_tile((char*)stK, kbatch + (size_t)(kt + 2) * TK * DIM, tid); CP_COMMIT();
        }
    }

    rs0 += __shfl_xor_sync(0xffffffffu, rs0, 1);
    rs0 += __shfl_xor_sync(0xffffffffu, rs0, 2);
    rs1 += __shfl_xor_sync(0xffffffffu, rs1, 1);
    rs1 += __shfl_xor_sync(0xffffffffu, rs1, 2);
    if (t == 0) {
        atomicAdd(&RI[m0 + g], rs0);
        atomicAdd(&RI[m0 + g + 8], rs1);
    }
    __syncthreads();
    if (tid < TQ) RI[tid] = 1.f / RI[tid];
    __syncthreads();

    const float inv0 = RI[m0 + g];
    const float inv1 = RI[m0 + g + 8];

    // ================= SWEEP 2 =================
    // PV split: warp w -> rows (w&7)*16, cols (w>>3)*64
    const int mw  = (w & 7) * 16;
    const int nwc = (w >> 3) * 64;
    float cacc[8][4];
    #pragma unroll
    for (int nb = 0; nb < 8; ++nb) { cacc[nb][0]=cacc[nb][1]=cacc[nb][2]=cacc[nb][3]=0.f; }

    // prologue: tile 0 K+V
    issue_tile((char*)stK, kbatch, tid);
    issue_tile((char*)stV, vbatch, tid);
    CP_COMMIT();
    CP_WAIT0();
    conv_tile(stK, Kt0, KS, tid);
    conv_tile(stV, Vh0, VHS, tid);
    __syncthreads();
    issue_tile((char*)stK, kbatch + (size_t)TK * DIM, tid);
    issue_tile((char*)stV, vbatch + (size_t)TK * DIM, tid);
    CP_COMMIT();

    float* attnbase = attn + ((size_t)(b * SEQ + q0)) * SEQ;

    for (int kt = 0; kt < NTILE; ++kt) {
        __half* Kc = Kt0 + (kt & 1) * (SZ_KB / 2);
        __half* Vc = Vh0 + (kt & 1) * (SZ_VB / 2);

        // --- QK recompute (identical sequence to sweep 1) ---
        float acc[4][4];
        #pragma unroll
        for (int j = 0; j < 4; ++j) { acc[j][0]=acc[j][1]=acc[j][2]=acc[j][3]=0.f; }
        #pragma unroll
        for (int kb2 = 0; kb2 < 8; ++kb2) {
            const int c0 = kb2 * 16 + t * 2;
            uint32_t a0 = *(const uint32_t*)(Qh + (m0 + g    ) * QS + c0);
            uint32_t a1 = *(const uint32_t*)(Qh + (m0 + g + 8) * QS + c0);
            uint32_t a2 = *(const uint32_t*)(Qh + (m0 + g    ) * QS + c0 + 8);
            uint32_t a3 = *(const uint32_t*)(Qh + (m0 + g + 8) * QS + c0 + 8);
            #pragma unroll
            for (int j = 0; j < 4; ++j) {
                const int n = (nh * 4 + j) * 8 + g;
                uint32_t b0 = *(const uint32_t*)(Kc + n * KS + c0);
                uint32_t b1 = *(const uint32_t*)(Kc + n * KS + c0 + 8);
                mma16816(acc[j], a0, a1, a2, a3, b0, b1);
            }
        }
        // normalized probabilities -> Ps
        #pragma unroll
        for (int j = 0; j < 4; ++j) {
            const int col = (nh * 4 + j) * 8 + t * 2;
            float2 p01, p23;
            p01.x = __expf(acc[j][0] * SCALE) * inv0;
            p01.y = __expf(acc[j][1] * SCALE) * inv0;
            p23.x = __expf(acc[j][2] * SCALE) * inv1;
            p23.y = __expf(acc[j][3] * SCALE) * inv1;
            *(float2*)(Ps + (m0 + g    ) * PSS + col) = p01;
            *(float2*)(Ps + (m0 + g + 8) * PSS + col) = p23;
        }
        __syncthreads();

        // --- attention streaming write ---
        float* ab = attnbase + kt * TK;
        #pragma unroll 4
        for (int i = tid; i < TQ * TK; i += THREADS) {
            int r = i >> 6, c = i & 63;
            __stcs(ab + (size_t)r * SEQ + c, Ps[r * PSS + c]);
        }

        // --- P @ V ---
        #pragma unroll
        for (int kb2 = 0; kb2 < 4; ++kb2) {
            const int s0 = kb2 * 16;
            const int c0 = s0 + t * 2;
            uint32_t A0, A1, A2, A3;
            {
                float2 f;
                f = *(const float2*)(Ps + (mw + g    ) * PSS + c0);     A0 = pack_f2(f.x, f.y);
                f = *(const float2*)(Ps + (mw + g + 8) * PSS + c0);     A1 = pack_f2(f.x, f.y);
                f = *(const float2*)(Ps + (mw + g    ) * PSS + c0 + 8); A2 = pack_f2(f.x, f.y);
                f = *(const float2*)(Ps + (mw + g + 8) * PSS + c0 + 8); A3 = pack_f2(f.x, f.y);
            }
            #pragma unroll
            for (int nb = 0; nb < 8; ++nb) {
                const int d0 = nwc + nb * 8;
                uint32_t b0, b1;
                ldmx2t(b0, b1, Vc + (s0 + lr) * VHS + d0);
                mma16816(cacc[nb], A0, A1, A2, A3, b0, b1);
            }
        }

        if (kt < NTILE - 1) {
            CP_WAIT0();
            conv_tile(stK, Kt0 + ((kt + 1) & 1) * (SZ_KB / 2), KS, tid);
            conv_tile(stV, Vh0 + ((kt + 1) & 1) * (SZ_VB / 2), VHS, tid);
        }
        __syncthreads();
        if (kt < NTILE - 2) {
            issue_tile((char*)stK, kbatch + (size_t)(kt + 2) * TK * DIM, tid);
            issue_tile((char*)stV, vbatch + (size_t)(kt + 2) * TK * DIM, tid);
            CP_COMMIT();
        }
    }

    // ---- write context ----
    float* cbase = ctx + ((size_t)(b * SEQ + q0)) * DIM;
    #pragma unroll
    for (int nb = 0; nb < 8; ++nb) {
        const int cc = nwc + nb * 8 + t * 2;
        float2 lo; lo.x = cacc[nb][0]; lo.y = cacc[nb][1];
        float2 hi; hi.x = cacc[nb][2]; hi.y = cacc[nb][3];
        *(float2*)(cbase + (size_t)(mw + g    ) * DIM + cc) = lo;
        *(float2*)(cbase + (size_t)(mw + g + 8) * DIM + cc) = hi;
    }
}

extern "C" void kernel_launch(void* const* d_in, const int* in_sizes, int n_in,
                              void* d_out, int out_size)
{
    const float* q = (const float*)d_in[0];
    const float* k = (const float*)d_in[1];
    const float* v = (const float*)d_in[2];
    float* out  = (float*)d_out;
    float* ctx  = out;                                 // [16,2048,128]
    float* attn = out + (size_t)BATCH * SEQ * DIM;     // [16,2048,2048]

    cudaFuncSetAttribute(attn_kernel, cudaFuncAttributeMaxDynamicSharedMemorySize, SMEM_BYTES);
    dim3 grid(SEQ / TQ, BATCH);
    attn_kernel<<<grid, THREADS, SMEM_BYTES>>>(q, k, v, ctx, attn);
}